// round 5
// baseline (speedup 1.0000x reference)
#include <cuda_runtime.h>
#include <cstdint>

// B=4096, T=1024, H=15
// Inputs: x[B*T], w_ih[15], w_hh[225], b_ih[15], b_hh[15], w_lin[15], b_lin[1]
// Output: out[B*T] float32
//
// Scalar layout: each 16-lane half-warp owns ONE batch. Lane i<15 owns hidden
// component i; lane 15 computes the linear head (one step delayed), buffers 4
// outputs in registers, and flushes with one STG.128 per 4 steps.
// No __syncthreads anywhere: x is broadcast-LDG'd per group (prefetched),
// h ping-pongs through 2 tiny smem buffers with one WARPSYNC per step.

#define T_      1024
#define THREADS 128           // 4 warps = 8 groups = 8 batches per CTA
#define GROUPS  8
#define BPC     8
#define GRID    (4096 / BPC)  // 512 CTAs

__device__ __forceinline__ float tanha(float x) {
    float r; asm("tanh.approx.f32 %0, %1;" : "=f"(r) : "f"(x)); return r;
}

__global__ void __launch_bounds__(THREADS)
rnn_kernel(const float* __restrict__ x,
           const float* __restrict__ w_ih, const float* __restrict__ w_hh,
           const float* __restrict__ b_ih, const float* __restrict__ b_hh,
           const float* __restrict__ w_lin, const float* __restrict__ b_lin,
           float* __restrict__ out)
{
    __shared__ __align__(16) float hbuf[2][GROUPS][16];   // 1KB; groups 64B apart

    const int tid  = threadIdx.x;
    const int lane = tid & 31;
    const int li   = lane & 15;
    const int g    = tid >> 4;              // 0..7: group (= batch) within CTA
    const int b0   = blockIdx.x * BPC;
    const bool is_head = (li == 15);

    // Per-lane weights
    float w[15], wih, bias;
    if (!is_head) {
#pragma unroll
        for (int j = 0; j < 15; j++) w[j] = w_hh[li * 15 + j];
        wih  = w_ih[li];
        bias = b_ih[li] + b_hh[li];
    } else {
#pragma unroll
        for (int j = 0; j < 15; j++) w[j] = w_lin[j];
        wih  = 0.0f;
        bias = b_lin[0];
    }

    hbuf[0][g][li] = 0.0f;                  // h0 = 0 (all 16 slots)
    __syncwarp();

    const float* xrow = x   + (size_t)(b0 + g) * T_;
    float*       orow = out + (size_t)(b0 + g) * T_;
    float* const hb0 = &hbuf[0][g][0];
    float* const hb1 = &hbuf[1][g][0];

    // Head output register buffer: o0..o3 hold out[4m-4 .. 4m-1] at flush time
    float o0 = 0.f, o1 = 0.f, o2 = 0.f, o3 = 0.f;

    // Prefetch x[0..3] (all 16 lanes of the group load the same float4)
    float4 xn = *reinterpret_cast<const float4*>(xrow);

#pragma unroll 1
    for (int m = 0; m < 256; ++m) {
        const float4 xc = xn;
        xn = *reinterpret_cast<const float4*>(xrow + (((m + 1) & 255) << 2));

#pragma unroll
        for (int u = 0; u < 4; ++u) {
            const float* hr = (u & 1) ? hb1 : hb0;
            float*       hw = (u & 1) ? hb0 : hb1;
            const float xv = (u == 0) ? xc.x : (u == 1) ? xc.y : (u == 2) ? xc.z : xc.w;

            // Broadcast-load h: 4x LDS.128 (slot 15 junk, never used)
            float h[16];
#pragma unroll
            for (int j = 0; j < 16; j += 4) {
                float4 v = *reinterpret_cast<const float4*>(hr + j);
                h[j] = v.x; h[j + 1] = v.y; h[j + 2] = v.z; h[j + 3] = v.w;
            }

            // 15-term matvec + input projection, 4-way tree
            float xp = fmaf(xv, wih, bias);
            float a0 = fmaf(w[0], h[0], xp);
            float a1 = w[1] * h[1];
            float a2 = w[2] * h[2];
            float a3 = w[3] * h[3];
#pragma unroll
            for (int j = 4; j < 12; j += 4) {
                a0 = fmaf(w[j + 0], h[j + 0], a0);
                a1 = fmaf(w[j + 1], h[j + 1], a1);
                a2 = fmaf(w[j + 2], h[j + 2], a2);
                a3 = fmaf(w[j + 3], h[j + 3], a3);
            }
            a0 = fmaf(w[12], h[12], a0);
            a1 = fmaf(w[13], h[13], a1);
            a2 = fmaf(w[14], h[14], a2);
            float acc = (a0 + a1) + (a2 + a3);

            hw[li] = tanha(acc);            // slot 15 junk, never read

            // Head lane: acc == out[s-1] for s = 4m+u  (s=0 value is junk,
            // never flushed). Slot: (s-1)&3 -> u=0:o3, u=1:o0, u=2:o1, u=3:o2.
            if (is_head) {
                if (u == 0) {
                    o3 = acc;
                    if (m > 0) {
                        float4 ov = make_float4(o0, o1, o2, o3);
                        *reinterpret_cast<float4*>(orow + ((m - 1) << 2)) = ov;
                    }
                } else if (u == 1) { o0 = acc; }
                else if (u == 2)   { o1 = acc; }
                else               { o2 = acc; }
            }
            __syncwarp();
        }
    }

    // Epilogue: "step 1024" head output from final h (in hb0 after 1024 steps).
    if (is_head) {
        float a0 = fmaf(w[0], hb0[0], bias);
        float a1 = w[1] * hb0[1];
        float a2 = w[2] * hb0[2];
        float a3 = w[3] * hb0[3];
#pragma unroll
        for (int j = 4; j < 12; j += 4) {
            a0 = fmaf(w[j + 0], hb0[j + 0], a0);
            a1 = fmaf(w[j + 1], hb0[j + 1], a1);
            a2 = fmaf(w[j + 2], hb0[j + 2], a2);
            a3 = fmaf(w[j + 3], hb0[j + 3], a3);
        }
        a0 = fmaf(w[12], hb0[12], a0);
        a1 = fmaf(w[13], hb0[13], a1);
        a2 = fmaf(w[14], hb0[14], a2);
        o3 = (a0 + a1) + (a2 + a3);         // out[1023]
        float4 ov = make_float4(o0, o1, o2, o3);
        *reinterpret_cast<float4*>(orow + (T_ - 4)) = ov;   // out[1020..1023]
    }
}

extern "C" void kernel_launch(void* const* d_in, const int* in_sizes, int n_in,
                              void* d_out, int out_size)
{
    const float* x     = (const float*)d_in[0];
    const float* w_ih  = (const float*)d_in[1];
    const float* w_hh  = (const float*)d_in[2];
    const float* b_ih  = (const float*)d_in[3];
    const float* b_hh  = (const float*)d_in[4];
    const float* w_lin = (const float*)d_in[5];
    const float* b_lin = (const float*)d_in[6];
    float* out = (float*)d_out;
    rnn_kernel<<<GRID, THREADS>>>(x, w_ih, w_hh, b_ih, b_hh, w_lin, b_lin, out);
}

// round 6
// speedup vs baseline: 1.1342x; 1.1342x over previous
#include <cuda_runtime.h>
#include <cstdint>

// B=4096, T=1024, H=15
// Inputs: x[B*T], w_ih[15], w_hh[225], b_ih[15], b_hh[15], w_lin[15], b_lin[1]
// Output: out[B*T] float32
//
// 8 lanes per batch; lane li (0..7) owns hidden rows 2li and 2li+1.
// Lane 7's second row is the linear head (row "15"), one step delayed.
// h exchange: 1x STS.64 + 2x LDS.128 + 1 syncwarp per step.
// 4 batches per warp, 16 per CTA, 256 CTAs.

#define T_      1024
#define THREADS 128
#define GROUPS  16            // batches per CTA (one per 8-lane group)
#define GRID    (4096 / GROUPS)
#define HSTRIDE 20            // floats per group: 80B, 16B-aligned, bank-quad disjoint

__device__ __forceinline__ float tanha(float x) {
    float r; asm("tanh.approx.f32 %0, %1;" : "=f"(r) : "f"(x)); return r;
}

__global__ void __launch_bounds__(THREADS)
rnn_kernel(const float* __restrict__ x,
           const float* __restrict__ w_ih, const float* __restrict__ w_hh,
           const float* __restrict__ b_ih, const float* __restrict__ b_hh,
           const float* __restrict__ w_lin, const float* __restrict__ b_lin,
           float* __restrict__ out)
{
    __shared__ __align__(16) float hbuf[2][GROUPS][HSTRIDE];   // 2.5KB

    const int tid  = threadIdx.x;
    const int lane = tid & 31;
    const int li   = lane & 7;           // lane within group
    const int g    = tid >> 3;           // 0..15: batch within CTA
    const int b0   = blockIdx.x * GROUPS;
    const bool is_head = (li == 7);

    // Rows 2li and 2li+1. Lane 7: row 14 (regular) + head row (w_lin).
    const int r0 = 2 * li, r1 = 2 * li + 1;
    float w0[15], w1[15], wih0, wih1, bias0, bias1;
#pragma unroll
    for (int j = 0; j < 15; j++) w0[j] = w_hh[r0 * 15 + j];
    wih0  = w_ih[r0];
    bias0 = b_ih[r0] + b_hh[r0];
    if (!is_head) {
#pragma unroll
        for (int j = 0; j < 15; j++) w1[j] = w_hh[r1 * 15 + j];
        wih1  = w_ih[r1];
        bias1 = b_ih[r1] + b_hh[r1];
    } else {
#pragma unroll
        for (int j = 0; j < 15; j++) w1[j] = w_lin[j];
        wih1  = 0.0f;
        bias1 = b_lin[0];
    }

    // h0 = 0
    hbuf[0][g][2 * li]     = 0.0f;
    hbuf[0][g][2 * li + 1] = 0.0f;
    __syncwarp();

    const float* xrow = x   + (size_t)(b0 + g) * T_;
    float*       optr = out + (size_t)(b0 + g) * T_;
    float* const hb0 = &hbuf[0][g][0];
    float* const hb1 = &hbuf[1][g][0];

    float o0 = 0.f, o1 = 0.f, o2 = 0.f, o3 = 0.f;

    float4 xn = *reinterpret_cast<const float4*>(xrow);   // x[0..3]

#pragma unroll 1
    for (int m = 0; m < 256; ++m) {
        const float4 xc = xn;
        const int mn = (m + 1) & 255;
        xn = *reinterpret_cast<const float4*>(xrow + (mn << 2));

#pragma unroll
        for (int u = 0; u < 4; ++u) {
            const float* hr = (u & 1) ? hb1 : hb0;
            float*       hw = (u & 1) ? hb0 : hb1;
            const float xv = (u == 0) ? xc.x : (u == 1) ? xc.y : (u == 2) ? xc.z : xc.w;

            // Broadcast-load h: 2x LDS.128 (slot 15 = stale head value, never used in dots)
            float h[16];
            {
                float4 v0 = *reinterpret_cast<const float4*>(hr + 0);
                float4 v1 = *reinterpret_cast<const float4*>(hr + 4);
                float4 v2 = *reinterpret_cast<const float4*>(hr + 8);
                float4 v3 = *reinterpret_cast<const float4*>(hr + 12);
                h[0]=v0.x; h[1]=v0.y; h[2]=v0.z; h[3]=v0.w;
                h[4]=v1.x; h[5]=v1.y; h[6]=v1.z; h[7]=v1.w;
                h[8]=v2.x; h[9]=v2.y; h[10]=v2.z; h[11]=v2.w;
                h[12]=v3.x; h[13]=v3.y; h[14]=v3.z; h[15]=v3.w;
            }

            // Two 15-term dot products (rows r0, r1), 2 accumulators each
            float xp0 = fmaf(xv, wih0, bias0);
            float xp1 = fmaf(xv, wih1, bias1);
            float a0 = fmaf(w0[0], h[0], xp0);
            float a1 = w0[1] * h[1];
            float c0 = fmaf(w1[0], h[0], xp1);
            float c1 = w1[1] * h[1];
#pragma unroll
            for (int j = 2; j < 14; j += 2) {
                a0 = fmaf(w0[j + 0], h[j + 0], a0);
                a1 = fmaf(w0[j + 1], h[j + 1], a1);
                c0 = fmaf(w1[j + 0], h[j + 0], c0);
                c1 = fmaf(w1[j + 1], h[j + 1], c1);
            }
            a0 = fmaf(w0[14], h[14], a0);
            c0 = fmaf(w1[14], h[14], c0);
            const float acc0 = a0 + a1;
            const float acc1 = c0 + c1;

            float t0 = tanha(acc0);
            float s1 = tanha(acc1);
            if (is_head) s1 = acc1;            // head slot stores raw head value
            *reinterpret_cast<float2*>(hw + 2 * li) = make_float2(t0, s1);

            // Head output schedule: acc1(lane7) == out[4m+u-1]
            if (u == 0) {
                o3 = acc1;
                if (m > 0 && is_head) {
                    *reinterpret_cast<float4*>(optr) = make_float4(o0, o1, o2, o3);
                }
                if (u == 0 && m > 0) optr += 4;    // uniform pointer advance
            } else if (u == 1) { o0 = acc1; }
            else if (u == 2)   { o1 = acc1; }
            else               { o2 = acc1; }
            __syncwarp();
        }
    }

    // Epilogue: out[1023] from final h (in hb0), flush out[1020..1023]
    if (is_head) {
        float c0 = bias1;
        float c1 = 0.0f;
#pragma unroll
        for (int j = 0; j < 14; j += 2) {
            c0 = fmaf(w1[j + 0], hb0[j + 0], c0);
            c1 = fmaf(w1[j + 1], hb0[j + 1], c1);
        }
        c0 = fmaf(w1[14], hb0[14], c0);
        o3 = c0 + c1;
        *reinterpret_cast<float4*>(optr) = make_float4(o0, o1, o2, o3);
    }
}

extern "C" void kernel_launch(void* const* d_in, const int* in_sizes, int n_in,
                              void* d_out, int out_size)
{
    const float* x     = (const float*)d_in[0];
    const float* w_ih  = (const float*)d_in[1];
    const float* w_hh  = (const float*)d_in[2];
    const float* b_ih  = (const float*)d_in[3];
    const float* b_hh  = (const float*)d_in[4];
    const float* w_lin = (const float*)d_in[5];
    const float* b_lin = (const float*)d_in[6];
    float* out = (float*)d_out;
    rnn_kernel<<<GRID, THREADS>>>(x, w_ih, w_hh, b_ih, b_hh, w_lin, b_lin, out);
}